// round 1
// baseline (speedup 1.0000x reference)
#include <cuda_runtime.h>
#include <math.h>

#define NP 8732
#define NG 16
#define NC 21
#define NTHREADS 512
#define NWARPS 16

__device__ double g_loss_l;
__device__ double g_loss_c;
__device__ unsigned long long g_num_pos;

__global__ void mb_zero() {
    g_loss_l = 0.0;
    g_loss_c = 0.0;
    g_num_pos = 0ull;
}

__global__ void __launch_bounds__(NTHREADS) mb_main(
    const float* __restrict__ loc_data,   // [B, NP, 10]
    const float* __restrict__ conf_data,  // [B, NP, 21]
    const float* __restrict__ priors,     // [NP, 4] (cx, cy, w, h)
    const float* __restrict__ targets)    // [B, NG, 11]
{
    __shared__ float s_ov[NP];            // pass1: best_truth_overlap ; pass2+: lc
    __shared__ float s_tg[NG * 11];
    __shared__ float s_bpv[NG * NWARPS];
    __shared__ int   s_bpi[NG * NWARPS];
    __shared__ int   s_bp[NG];
    __shared__ float s_rf[NWARPS];
    __shared__ float s_rf2[NWARPS];
    __shared__ int   s_ri[NWARPS];
    __shared__ int   s_bc[4];
    __shared__ unsigned s_gsum[NWARPS];
    __shared__ unsigned s_histmem[2184];  // 8736 B: alias = best_truth_idx bytes / radix hist
    unsigned char* s_idx = (unsigned char*)s_histmem;

    const int b    = blockIdx.x;
    const int tid  = threadIdx.x;
    const int lane = tid & 31;
    const int wrp  = tid >> 5;

    // ---- load targets for this batch ----
    for (int i = tid; i < NG * 11; i += NTHREADS)
        s_tg[i] = targets[b * NG * 11 + i];
    __syncthreads();

    // ---- pass 1: IoU matching ----
    float bv[NG];
    int   bi[NG];
#pragma unroll
    for (int g = 0; g < NG; g++) { bv[g] = -1e30f; bi[g] = 0x7fffffff; }

    for (int p = tid; p < NP; p += NTHREADS) {
        float4 pr = __ldg((const float4*)priors + p);
        float pax = pr.x - 0.5f * pr.z;
        float pay = pr.y - 0.5f * pr.w;
        float pbx = pr.x + 0.5f * pr.z;
        float pby = pr.y + 0.5f * pr.w;
        float pare = (pbx - pax) * (pby - pay);
        float bestv = -1e30f;
        int   bestg = 0;
#pragma unroll
        for (int g = 0; g < NG; g++) {
            const float* t = s_tg + g * 11;
            float ix = fminf(t[2], pbx) - fmaxf(t[0], pax);
            float iy = fminf(t[3], pby) - fmaxf(t[1], pay);
            ix = fmaxf(ix, 0.0f);
            iy = fmaxf(iy, 0.0f);
            float inter = ix * iy;
            float aa = (t[2] - t[0]) * (t[3] - t[1]);
            float iou = inter / (aa + pare - inter);
            if (iou > bestv) { bestv = iou; bestg = g; }   // first-max over g
            if (iou > bv[g]) { bv[g] = iou; bi[g] = p; }   // p ascending -> first-max over p
        }
        s_ov[p]  = bestv;
        s_idx[p] = (unsigned char)bestg;
    }

    // reduce best prior per gt (val desc, idx asc tiebreak)
#pragma unroll
    for (int g = 0; g < NG; g++) {
        float v = bv[g];
        int   i = bi[g];
#pragma unroll
        for (int o = 16; o > 0; o >>= 1) {
            float v2 = __shfl_down_sync(0xffffffffu, v, o);
            int   i2 = __shfl_down_sync(0xffffffffu, i, o);
            if (v2 > v || (v2 == v && i2 < i)) { v = v2; i = i2; }
        }
        if (lane == 0) { s_bpv[g * NWARPS + wrp] = v; s_bpi[g * NWARPS + wrp] = i; }
    }
    __syncthreads();
    if (tid < NG) {
        float v = s_bpv[tid * NWARPS];
        int   i = s_bpi[tid * NWARPS];
        for (int w = 1; w < NWARPS; w++) {
            float v2 = s_bpv[tid * NWARPS + w];
            int   i2 = s_bpi[tid * NWARPS + w];
            if (v2 > v || (v2 == v && i2 < i)) { v = v2; i = i2; }
        }
        s_bp[tid] = i;
    }
    __syncthreads();
    if (tid == 0) {
#pragma unroll
        for (int g = 0; g < NG; g++) s_ov[s_bp[g]] = 2.0f;
#pragma unroll
        for (int j = 0; j < NG; j++) s_idx[s_bp[j]] = (unsigned char)j;  // sequential, last wins
    }
    __syncthreads();

    // ---- pass 2: losses per prior ----
    float ll  = 0.0f;   // smooth-L1 partial (pos only)
    float lcp = 0.0f;   // conf loss over pos
    int   np  = 0;
    for (int p = tid; p < NP; p += NTHREADS) {
        float ov = s_ov[p];
        int   gi = s_idx[p];
        const float* t = s_tg + gi * 11;
        int conf = 0;
        if (!(ov < 0.5f)) conf = (int)t[10] + 1;

        const float* c = conf_data + ((size_t)b * NP + p) * NC;
        float cv[NC];
#pragma unroll
        for (int j = 0; j < NC; j++) cv[j] = __ldg(c + j);
        float m = cv[0];
#pragma unroll
        for (int j = 1; j < NC; j++) m = fmaxf(m, cv[j]);
        float s = 0.0f;
#pragma unroll
        for (int j = 0; j < NC; j++) s += expf(cv[j] - m);
        float tl = cv[0];
#pragma unroll
        for (int j = 1; j < NC; j++) tl = (conf == j) ? cv[j] : tl;
        float lca = (m + logf(s)) - tl;

        float lc = lca;
        if (conf > 0) {
            lc = 0.0f;
            np++;
            lcp += lca;
            float4 pr = __ldg((const float4*)priors + p);
            float vx = 0.1f * pr.z;
            float vy = 0.1f * pr.w;
            float lts[10];
            lts[0] = ((t[0] + t[2]) * 0.5f - pr.x) / vx;
            lts[1] = ((t[1] + t[3]) * 0.5f - pr.y) / vy;
            lts[2] = logf((t[2] - t[0]) / pr.z) / 0.2f;
            lts[3] = logf((t[3] - t[1]) / pr.w) / 0.2f;
            lts[4] = logf(t[4] / pr.z + 0.1f) / 0.2f;
            lts[5] = logf(t[5] / pr.w + 0.1f) / 0.2f;
            lts[6] = logf(t[6] / pr.z + 0.1f) / 0.2f;
            lts[7] = logf(t[7] / pr.w + 0.1f) / 0.2f;
            lts[8] = (t[8] - pr.x) / vx;
            lts[9] = (t[9] - pr.y) / vy;
            const float* ld = loc_data + ((size_t)b * NP + p) * 10;
#pragma unroll
            for (int j = 0; j < 10; j++) {
                float d  = __ldg(ld + j) - lts[j];
                float ad = fabsf(d);
                ll += (ad < 1.0f) ? (0.5f * d) * d : (ad - 0.5f);
            }
        }
        s_ov[p] = lc;  // reuse array as lc
    }
    __syncthreads();

    // ---- block reduce np / ll / lcp ----
#pragma unroll
    for (int o = 16; o > 0; o >>= 1) {
        ll  += __shfl_down_sync(0xffffffffu, ll, o);
        lcp += __shfl_down_sync(0xffffffffu, lcp, o);
        np  += __shfl_down_sync(0xffffffffu, np, o);
    }
    if (lane == 0) { s_rf[wrp] = ll; s_rf2[wrp] = lcp; s_ri[wrp] = np; }
    __syncthreads();
    float ll_t = 0.0f, lcp_t = 0.0f;
    int   np_t = 0;
    if (tid < NWARPS) { ll_t = s_rf[tid]; lcp_t = s_rf2[tid]; np_t = s_ri[tid]; }
    if (tid < 32) {
#pragma unroll
        for (int o = 8; o > 0; o >>= 1) {
            ll_t  += __shfl_down_sync(0xffffffffu, ll_t, o);
            lcp_t += __shfl_down_sync(0xffffffffu, lcp_t, o);
            np_t  += __shfl_down_sync(0xffffffffu, np_t, o);
        }
    }
    if (tid == 0) s_bc[0] = np_t;
    __syncthreads();
    const int np_tot = s_bc[0];
    int k = 3 * np_tot;
    if (k > NP - 1) k = NP - 1;

    // ---- exact top-k sum of lc via 3-round radix select (lc >= 0) ----
    float S = 0.0f;
    if (k > 0) {
        unsigned prefix = 0u, pmask = 0u;
        const int shifts[3] = {21, 10, 0};
        const int rbits[3]  = {11, 11, 10};
        int kk = k;
        for (int r = 0; r < 3; r++) {
            for (int i = tid; i < 2048; i += NTHREADS) s_histmem[i] = 0u;
            __syncthreads();
            const int nb = 1 << rbits[r];
            for (int p = tid; p < NP; p += NTHREADS) {
                unsigned bb = __float_as_uint(s_ov[p]);
                if ((bb & pmask) == prefix)
                    atomicAdd(&s_histmem[(bb >> shifts[r]) & (nb - 1)], 1u);
            }
            __syncthreads();
            unsigned gv = s_histmem[tid * 4] + s_histmem[tid * 4 + 1] +
                          s_histmem[tid * 4 + 2] + s_histmem[tid * 4 + 3];
#pragma unroll
            for (int o = 16; o > 0; o >>= 1) gv += __shfl_down_sync(0xffffffffu, gv, o);
            if (lane == 0) s_gsum[wrp] = gv;
            __syncthreads();
            if (tid == 0) {
                int cum = 0, grp = 0;
                for (int g2 = NWARPS - 1; g2 >= 0; g2--) {
                    int cc = (int)s_gsum[g2];
                    if (cum + cc >= kk) { grp = g2; break; }
                    cum += cc;
                }
                int chosen = grp * 128;
                for (int bin = grp * 128 + 127; bin >= grp * 128; bin--) {
                    int cc = (int)s_histmem[bin];
                    if (cum + cc >= kk) { chosen = bin; kk -= cum; break; }
                    cum += cc;
                }
                s_bc[1] = chosen;
                s_bc[2] = kk;
            }
            __syncthreads();
            int chosen = s_bc[1];
            kk = s_bc[2];
            prefix |= ((unsigned)chosen) << shifts[r];
            pmask  |= ((1u << rbits[r]) - 1u) << shifts[r];
        }
        const float tv = __uint_as_float(prefix);
        float sgt = 0.0f;
        int   cgt = 0;
        for (int p = tid; p < NP; p += NTHREADS) {
            float v = s_ov[p];
            if (__float_as_uint(v) > prefix) { sgt += v; cgt++; }
        }
#pragma unroll
        for (int o = 16; o > 0; o >>= 1) {
            sgt += __shfl_down_sync(0xffffffffu, sgt, o);
            cgt += __shfl_down_sync(0xffffffffu, cgt, o);
        }
        __syncthreads();
        if (lane == 0) { s_rf[wrp] = sgt; s_ri[wrp] = cgt; }
        __syncthreads();
        float sgt_t = 0.0f;
        int   cgt_t = 0;
        if (tid < NWARPS) { sgt_t = s_rf[tid]; cgt_t = s_ri[tid]; }
        if (tid < 32) {
#pragma unroll
            for (int o = 8; o > 0; o >>= 1) {
                sgt_t += __shfl_down_sync(0xffffffffu, sgt_t, o);
                cgt_t += __shfl_down_sync(0xffffffffu, cgt_t, o);
            }
        }
        if (tid == 0) S = sgt_t + (float)(k - cgt_t) * tv;
    }

    if (tid == 0) {
        atomicAdd(&g_loss_l, (double)ll_t);
        atomicAdd(&g_loss_c, (double)(lcp_t + S));
        atomicAdd(&g_num_pos, (unsigned long long)np_tot);
    }
}

__global__ void mb_finalize(float* out) {
    float N = (float)g_num_pos;
    out[0] = (float)g_loss_l / N;
    out[1] = (float)g_loss_c / N;
}

extern "C" void kernel_launch(void* const* d_in, const int* in_sizes, int n_in,
                              void* d_out, int out_size) {
    const float* loc     = (const float*)d_in[0];
    const float* conf    = (const float*)d_in[1];
    const float* priors  = (const float*)d_in[2];
    const float* targets = (const float*)d_in[3];
    const int B = in_sizes[0] / (NP * 10);

    mb_zero<<<1, 1>>>();
    mb_main<<<B, NTHREADS>>>(loc, conf, priors, targets);
    mb_finalize<<<1, 1>>>((float*)d_out);
}

// round 2
// speedup vs baseline: 1.0341x; 1.0341x over previous
#include <cuda_runtime.h>
#include <math.h>

#define NP 8732
#define NG 16
#define NC 21
#define NTHREADS 512
#define NWARPS 16
#define NTILES 273   // ceil(8732/32)

__device__ float g_bll[256];
__device__ float g_blc[256];
__device__ int   g_bnp[256];

struct Smem {
    float ov[NP];                 // pass1: best overlap ; pass2+: lc
    float stage[NWARPS * 672];    // conf staging (aliased as radix hist later)
    unsigned char idx[NP + 4];    // best gt per prior
    float tg[NG * 11];
    float bpv[NG * NWARPS];
    int   bpi[NG * NWARPS];
    int   bp[NG];
    float rf[NWARPS];
    float rf2[NWARPS];
    int   ri[NWARPS];
    int   bc[4];
    unsigned gsum[NWARPS];
};

__global__ void __launch_bounds__(NTHREADS) mb_main(
    const float* __restrict__ loc_data,   // [B, NP, 10]
    const float* __restrict__ conf_data,  // [B, NP, 21]
    const float* __restrict__ priors,     // [NP, 4]
    const float* __restrict__ targets)    // [B, NG, 11]
{
    extern __shared__ char smem_raw[];
    Smem* S = (Smem*)smem_raw;
    unsigned* hist = (unsigned*)S->stage;   // alias, used after staging is dead

    const int b    = blockIdx.x;
    const int tid  = threadIdx.x;
    const int lane = tid & 31;
    const int wrp  = tid >> 5;

    // ---- load targets ----
    for (int i = tid; i < NG * 11; i += NTHREADS)
        S->tg[i] = targets[b * NG * 11 + i];
    __syncthreads();

    // ---- pass 1: IoU matching (exact IEEE ops -> decisions match reference) ----
    float bv[NG];
    int   bi[NG];
#pragma unroll
    for (int g = 0; g < NG; g++) { bv[g] = -1e30f; bi[g] = 0x7fffffff; }

    for (int p = tid; p < NP; p += NTHREADS) {
        float4 pr = __ldg((const float4*)priors + p);
        float pax = pr.x - 0.5f * pr.z;
        float pay = pr.y - 0.5f * pr.w;
        float pbx = pr.x + 0.5f * pr.z;
        float pby = pr.y + 0.5f * pr.w;
        float pare = (pbx - pax) * (pby - pay);
        float bestv = -1e30f;
        int   bestg = 0;
#pragma unroll
        for (int g = 0; g < NG; g++) {
            const float* t = S->tg + g * 11;
            float ix = fminf(t[2], pbx) - fmaxf(t[0], pax);
            float iy = fminf(t[3], pby) - fmaxf(t[1], pay);
            ix = fmaxf(ix, 0.0f);
            iy = fmaxf(iy, 0.0f);
            float inter = ix * iy;
            float aa = (t[2] - t[0]) * (t[3] - t[1]);
            float iou = inter / (aa + pare - inter);
            if (iou > bestv) { bestv = iou; bestg = g; }
            if (iou > bv[g]) { bv[g] = iou; bi[g] = p; }
        }
        S->ov[p]  = bestv;
        S->idx[p] = (unsigned char)bestg;
    }

#pragma unroll
    for (int g = 0; g < NG; g++) {
        float v = bv[g];
        int   i = bi[g];
#pragma unroll
        for (int o = 16; o > 0; o >>= 1) {
            float v2 = __shfl_down_sync(0xffffffffu, v, o);
            int   i2 = __shfl_down_sync(0xffffffffu, i, o);
            if (v2 > v || (v2 == v && i2 < i)) { v = v2; i = i2; }
        }
        if (lane == 0) { S->bpv[g * NWARPS + wrp] = v; S->bpi[g * NWARPS + wrp] = i; }
    }
    __syncthreads();
    if (tid < NG) {
        float v = S->bpv[tid * NWARPS];
        int   i = S->bpi[tid * NWARPS];
        for (int w = 1; w < NWARPS; w++) {
            float v2 = S->bpv[tid * NWARPS + w];
            int   i2 = S->bpi[tid * NWARPS + w];
            if (v2 > v || (v2 == v && i2 < i)) { v = v2; i = i2; }
        }
        S->bp[tid] = i;
    }
    __syncthreads();
    if (tid == 0) {
#pragma unroll
        for (int g = 0; g < NG; g++) S->ov[S->bp[g]] = 2.0f;
#pragma unroll
        for (int j = 0; j < NG; j++) S->idx[S->bp[j]] = (unsigned char)j;
    }
    __syncthreads();

    // ---- pass 2: losses, warp-tiled with coalesced conf staging ----
    float ll  = 0.0f;
    float lcp = 0.0f;
    int   np  = 0;
    float* stg = S->stage + wrp * 672;

    for (int tile = wrp; tile < NTILES; tile += NWARPS) {
        const int p0 = tile * 32;
        const int cnt = (NP - p0 < 32) ? (NP - p0) : 32;
        const int tcnt = cnt * NC;
        const float* cbase = conf_data + ((size_t)b * NP + p0) * NC;
#pragma unroll
        for (int j = 0; j < NC; j++) {
            int idx2 = j * 32 + lane;
            if (idx2 < tcnt) stg[idx2] = __ldg(cbase + idx2);
        }
        __syncwarp();

        const int p = p0 + lane;
        if (p < NP) {
            float ov = S->ov[p];
            int   gi = S->idx[p];
            const float* t = S->tg + gi * 11;
            int conf = 0;
            if (!(ov < 0.5f)) conf = (int)t[10] + 1;

            const float* row = stg + lane * NC;
            float cv[NC];
#pragma unroll
            for (int j = 0; j < NC; j++) cv[j] = row[j];
            float m = cv[0];
#pragma unroll
            for (int j = 1; j < NC; j++) m = fmaxf(m, cv[j]);
            float s = 0.0f;
#pragma unroll
            for (int j = 0; j < NC; j++) s += __expf(cv[j] - m);
            float tl = cv[0];
#pragma unroll
            for (int j = 1; j < NC; j++) tl = (conf == j) ? cv[j] : tl;
            float lca = (m + __logf(s)) - tl;

            float lc = lca;
            if (conf > 0) {
                lc = 0.0f;
                np++;
                lcp += lca;
                float4 pr = __ldg((const float4*)priors + p);
                float vx = 0.1f * pr.z;
                float vy = 0.1f * pr.w;
                float lts[10];
                lts[0] = ((t[0] + t[2]) * 0.5f - pr.x) / vx;
                lts[1] = ((t[1] + t[3]) * 0.5f - pr.y) / vy;
                lts[2] = logf((t[2] - t[0]) / pr.z) / 0.2f;
                lts[3] = logf((t[3] - t[1]) / pr.w) / 0.2f;
                lts[4] = logf(t[4] / pr.z + 0.1f) / 0.2f;
                lts[5] = logf(t[5] / pr.w + 0.1f) / 0.2f;
                lts[6] = logf(t[6] / pr.z + 0.1f) / 0.2f;
                lts[7] = logf(t[7] / pr.w + 0.1f) / 0.2f;
                lts[8] = (t[8] - pr.x) / vx;
                lts[9] = (t[9] - pr.y) / vy;
                const float* ld = loc_data + ((size_t)b * NP + p) * 10;
#pragma unroll
                for (int j = 0; j < 10; j++) {
                    float d  = __ldg(ld + j) - lts[j];
                    float ad = fabsf(d);
                    ll += (ad < 1.0f) ? (0.5f * d) * d : (ad - 0.5f);
                }
            }
            S->ov[p] = lc;
        }
        __syncwarp();
    }
    __syncthreads();

    // ---- block reduce np / ll / lcp ----
#pragma unroll
    for (int o = 16; o > 0; o >>= 1) {
        ll  += __shfl_down_sync(0xffffffffu, ll, o);
        lcp += __shfl_down_sync(0xffffffffu, lcp, o);
        np  += __shfl_down_sync(0xffffffffu, np, o);
    }
    if (lane == 0) { S->rf[wrp] = ll; S->rf2[wrp] = lcp; S->ri[wrp] = np; }
    __syncthreads();
    float ll_t = 0.0f, lcp_t = 0.0f;
    int   np_t = 0;
    if (tid < NWARPS) { ll_t = S->rf[tid]; lcp_t = S->rf2[tid]; np_t = S->ri[tid]; }
    if (tid < 32) {
#pragma unroll
        for (int o = 8; o > 0; o >>= 1) {
            ll_t  += __shfl_down_sync(0xffffffffu, ll_t, o);
            lcp_t += __shfl_down_sync(0xffffffffu, lcp_t, o);
            np_t  += __shfl_down_sync(0xffffffffu, np_t, o);
        }
    }
    if (tid == 0) S->bc[0] = np_t;
    __syncthreads();
    const int np_tot = S->bc[0];
    int k = 3 * np_tot;
    if (k > NP - 1) k = NP - 1;

    // ---- exact top-k sum via 3-round radix select on lc bit patterns ----
    float Ssum = 0.0f;
    if (k > 0) {
        unsigned prefix = 0u, pmask = 0u;
        const int shifts[3] = {21, 10, 0};
        const int rbits[3]  = {11, 11, 10};
        int kk = k;
        for (int r = 0; r < 3; r++) {
            for (int i = tid; i < 2048; i += NTHREADS) hist[i] = 0u;
            __syncthreads();
            const int nb = 1 << rbits[r];
            for (int p = tid; p < NP; p += NTHREADS) {
                unsigned bb = __float_as_uint(S->ov[p]);
                if ((bb & pmask) == prefix)
                    atomicAdd(&hist[(bb >> shifts[r]) & (nb - 1)], 1u);
            }
            __syncthreads();
            unsigned gv = hist[tid * 4] + hist[tid * 4 + 1] +
                          hist[tid * 4 + 2] + hist[tid * 4 + 3];
#pragma unroll
            for (int o = 16; o > 0; o >>= 1) gv += __shfl_down_sync(0xffffffffu, gv, o);
            if (lane == 0) S->gsum[wrp] = gv;
            __syncthreads();
            if (tid == 0) {
                int cum = 0, grp = 0;
                for (int g2 = NWARPS - 1; g2 >= 0; g2--) {
                    int cc = (int)S->gsum[g2];
                    if (cum + cc >= kk) { grp = g2; break; }
                    cum += cc;
                }
                int chosen = grp * 128;
                for (int bin = grp * 128 + 127; bin >= grp * 128; bin--) {
                    int cc = (int)hist[bin];
                    if (cum + cc >= kk) { chosen = bin; kk -= cum; break; }
                    cum += cc;
                }
                S->bc[1] = chosen;
                S->bc[2] = kk;
            }
            __syncthreads();
            int chosen = S->bc[1];
            kk = S->bc[2];
            prefix |= ((unsigned)chosen) << shifts[r];
            pmask  |= ((1u << rbits[r]) - 1u) << shifts[r];
        }
        const float tv = __uint_as_float(prefix);
        float sgt = 0.0f;
        int   cgt = 0;
        for (int p = tid; p < NP; p += NTHREADS) {
            float v = S->ov[p];
            if (__float_as_uint(v) > prefix) { sgt += v; cgt++; }
        }
#pragma unroll
        for (int o = 16; o > 0; o >>= 1) {
            sgt += __shfl_down_sync(0xffffffffu, sgt, o);
            cgt += __shfl_down_sync(0xffffffffu, cgt, o);
        }
        __syncthreads();
        if (lane == 0) { S->rf[wrp] = sgt; S->ri[wrp] = cgt; }
        __syncthreads();
        float sgt_t = 0.0f;
        int   cgt_t = 0;
        if (tid < NWARPS) { sgt_t = S->rf[tid]; cgt_t = S->ri[tid]; }
        if (tid < 32) {
#pragma unroll
            for (int o = 8; o > 0; o >>= 1) {
                sgt_t += __shfl_down_sync(0xffffffffu, sgt_t, o);
                cgt_t += __shfl_down_sync(0xffffffffu, cgt_t, o);
            }
        }
        if (tid == 0) Ssum = sgt_t + (float)(k - cgt_t) * tv;
    }

    if (tid == 0) {
        g_bll[b] = ll_t;
        g_blc[b] = lcp_t + Ssum;
        g_bnp[b] = np_tot;
    }
}

__global__ void mb_finalize(float* out, int B) {
    const int tid = threadIdx.x;
    float ll = 0.0f, lc = 0.0f;
    int   np = 0;
    if (tid < B) { ll = g_bll[tid]; lc = g_blc[tid]; np = g_bnp[tid]; }
    __shared__ float srf[8], srf2[8];
    __shared__ int   sri[8];
#pragma unroll
    for (int o = 16; o > 0; o >>= 1) {
        ll += __shfl_down_sync(0xffffffffu, ll, o);
        lc += __shfl_down_sync(0xffffffffu, lc, o);
        np += __shfl_down_sync(0xffffffffu, np, o);
    }
    if ((tid & 31) == 0) { srf[tid >> 5] = ll; srf2[tid >> 5] = lc; sri[tid >> 5] = np; }
    __syncthreads();
    if (tid == 0) {
        float llt = 0.0f, lct = 0.0f;
        int npt = 0;
        for (int w = 0; w < (B + 31) / 32; w++) { llt += srf[w]; lct += srf2[w]; npt += sri[w]; }
        float N = (float)npt;
        out[0] = llt / N;
        out[1] = lct / N;
    }
}

extern "C" void kernel_launch(void* const* d_in, const int* in_sizes, int n_in,
                              void* d_out, int out_size) {
    const float* loc     = (const float*)d_in[0];
    const float* conf    = (const float*)d_in[1];
    const float* priors  = (const float*)d_in[2];
    const float* targets = (const float*)d_in[3];
    const int B = in_sizes[0] / (NP * 10);

    cudaFuncSetAttribute(mb_main, cudaFuncAttributeMaxDynamicSharedMemorySize,
                         (int)sizeof(Smem));
    mb_main<<<B, NTHREADS, sizeof(Smem)>>>(loc, conf, priors, targets);
    mb_finalize<<<1, 256>>>((float*)d_out, B);
}

// round 3
// speedup vs baseline: 1.6356x; 1.5816x over previous
#include <cuda_runtime.h>
#include <math.h>

#define NP 8732
#define NG 16
#define NC 21
#define NTHREADS 512
#define NWARPS 16
#define NTILES 273

__device__ float g_bll[256];
__device__ float g_blc[256];
__device__ int   g_bnp[256];
__device__ unsigned g_arrive = 0;

struct Smem {
    float4 box[NG];                // gt point-form boxes
    float  taa[NG];                // gt areas
    float  lc[NP];
    float  stage[NWARPS * 672];    // conf staging; aliased as radix hist (8KB) later
    float  tg[NG * 11];
    unsigned char gi[NP + 4];
    unsigned char pos[NP + 4];
    float  riv[NG * NWARPS];
    float  rdv[NG * NWARPS];
    int    rbi[NG * NWARPS];
    int    bp[NG];
    float  rf[NWARPS];
    float  rf2[NWARPS];
    int    ri[NWARPS];
    unsigned gsum[NWARPS];
    int    bc[4];
};

__global__ void __launch_bounds__(NTHREADS) mb_main(
    const float* __restrict__ loc_data,   // [B, NP, 10]
    const float* __restrict__ conf_data,  // [B, NP, 21]
    const float* __restrict__ priors,     // [NP, 4]
    const float* __restrict__ targets,    // [B, NG, 11]
    float* __restrict__ out)
{
    extern __shared__ char smem_raw[];
    Smem* S = (Smem*)smem_raw;
    unsigned* hist = (unsigned*)S->stage;

    const int b    = blockIdx.x;
    const int tid  = threadIdx.x;
    const int lane = tid & 31;
    const int wrp  = tid >> 5;

    for (int i = tid; i < NG * 11; i += NTHREADS)
        S->tg[i] = targets[b * NG * 11 + i];
    __syncthreads();
    if (tid < NG) {
        const float* t = S->tg + tid * 11;
        float4 bx = make_float4(t[0], t[1], t[2], t[3]);
        S->box[tid] = bx;
        S->taa[tid] = (bx.z - bx.x) * (bx.w - bx.y);
    }
    __syncthreads();

    // ---- pass 1: IoU matching via rational comparisons (no divisions) ----
    float iv[NG], dv[NG];
    int   bi_[NG];
#pragma unroll
    for (int g = 0; g < NG; g++) { iv[g] = -1.0f; dv[g] = 1.0f; bi_[g] = 0x7fffffff; }

    for (int p = tid; p < NP; p += NTHREADS) {
        float4 pr = __ldg((const float4*)priors + p);
        float pax = pr.x - 0.5f * pr.z;
        float pay = pr.y - 0.5f * pr.w;
        float pbx = pr.x + 0.5f * pr.z;
        float pby = pr.y + 0.5f * pr.w;
        float pare = (pbx - pax) * (pby - pay);
        float bin_ = -1.0f, bdn_ = 1.0f;
        int bg = 0;
#pragma unroll
        for (int g = 0; g < NG; g++) {
            float4 t = S->box[g];
            float ix = fminf(t.z, pbx) - fmaxf(t.x, pax);
            float iy = fminf(t.w, pby) - fmaxf(t.y, pay);
            ix = fmaxf(ix, 0.0f);
            iy = fmaxf(iy, 0.0f);
            float inter = ix * iy;
            float den = (S->taa[g] + pare) - inter;   // > 0 always
            if (inter * bdn_ > bin_ * den) { bin_ = inter; bdn_ = den; bg = g; }
            if (inter * dv[g] > iv[g] * den) { iv[g] = inter; dv[g] = den; bi_[g] = p; }
        }
        S->gi[p]  = (unsigned char)bg;
        S->pos[p] = (bin_ >= 0.5f * bdn_) ? 1 : 0;    // 0.5*den exact
    }

    // reduce best prior per gt (rational value desc, idx asc tiebreak)
#pragma unroll
    for (int g = 0; g < NG; g++) {
        float a = iv[g], d = dv[g];
        int   i = bi_[g];
#pragma unroll
        for (int o = 16; o > 0; o >>= 1) {
            float a2 = __shfl_down_sync(0xffffffffu, a, o);
            float d2 = __shfl_down_sync(0xffffffffu, d, o);
            int   i2 = __shfl_down_sync(0xffffffffu, i, o);
            float l = a2 * d, r = a * d2;
            if (l > r || (l == r && i2 < i)) { a = a2; d = d2; i = i2; }
        }
        if (lane == 0) {
            S->riv[g * NWARPS + wrp] = a;
            S->rdv[g * NWARPS + wrp] = d;
            S->rbi[g * NWARPS + wrp] = i;
        }
    }
    __syncthreads();
    if (tid < NG) {
        float a = S->riv[tid * NWARPS], d = S->rdv[tid * NWARPS];
        int   i = S->rbi[tid * NWARPS];
        for (int w = 1; w < NWARPS; w++) {
            float a2 = S->riv[tid * NWARPS + w];
            float d2 = S->rdv[tid * NWARPS + w];
            int   i2 = S->rbi[tid * NWARPS + w];
            float l = a2 * d, r = a * d2;
            if (l > r || (l == r && i2 < i)) { a = a2; d = d2; i = i2; }
        }
        S->bp[tid] = i;
    }
    __syncthreads();
    if (tid == 0) {
#pragma unroll
        for (int g = 0; g < NG; g++) S->pos[S->bp[g]] = 1;     // the 2.0 override
#pragma unroll
        for (int j = 0; j < NG; j++) S->gi[S->bp[j]] = (unsigned char)j;
    }
    __syncthreads();

    // ---- pass 2: per-prior losses (warp-tiled coalesced conf staging) ----
    float ll = 0.0f, lcp = 0.0f;
    int   np = 0;
    float* stg = S->stage + wrp * 672;

    for (int tile = wrp; tile < NTILES; tile += NWARPS) {
        const int p0 = tile * 32;
        const int cnt = (NP - p0 < 32) ? (NP - p0) : 32;
        const int tcnt = cnt * NC;
        const float* cbase = conf_data + ((size_t)b * NP + p0) * NC;
#pragma unroll
        for (int j = 0; j < NC; j++) {
            int idx2 = j * 32 + lane;
            if (idx2 < tcnt) stg[idx2] = __ldg(cbase + idx2);
        }
        __syncwarp();

        const int p = p0 + lane;
        if (p < NP) {
            int gi = S->gi[p];
            int conf = S->pos[p] ? ((int)S->tg[gi * 11 + 10] + 1) : 0;

            const float* row = stg + lane * NC;
            float cv[NC];
#pragma unroll
            for (int j = 0; j < NC; j++) cv[j] = row[j];
            float m = cv[0];
#pragma unroll
            for (int j = 1; j < NC; j++) m = fmaxf(m, cv[j]);
            float s = 0.0f;
#pragma unroll
            for (int j = 0; j < NC; j++) s += __expf(cv[j] - m);
            float tl = row[conf];
            float lca = (m + __logf(s)) - tl;

            float lc = lca;
            if (conf > 0) {
                lc = 0.0f;
                np++;
                lcp += lca;
                const float* t = S->tg + gi * 11;
                float4 pr = __ldg((const float4*)priors + p);
                float vx = 0.1f * pr.z;
                float vy = 0.1f * pr.w;
                float lts[10];
                lts[0] = ((t[0] + t[2]) * 0.5f - pr.x) / vx;
                lts[1] = ((t[1] + t[3]) * 0.5f - pr.y) / vy;
                lts[2] = logf((t[2] - t[0]) / pr.z) / 0.2f;
                lts[3] = logf((t[3] - t[1]) / pr.w) / 0.2f;
                lts[4] = logf(t[4] / pr.z + 0.1f) / 0.2f;
                lts[5] = logf(t[5] / pr.w + 0.1f) / 0.2f;
                lts[6] = logf(t[6] / pr.z + 0.1f) / 0.2f;
                lts[7] = logf(t[7] / pr.w + 0.1f) / 0.2f;
                lts[8] = (t[8] - pr.x) / vx;
                lts[9] = (t[9] - pr.y) / vy;
                const float* ld = loc_data + ((size_t)b * NP + p) * 10;
#pragma unroll
                for (int j = 0; j < 10; j++) {
                    float d  = __ldg(ld + j) - lts[j];
                    float ad = fabsf(d);
                    ll += (ad < 1.0f) ? (0.5f * d) * d : (ad - 0.5f);
                }
            }
            S->lc[p] = lc;
        }
        __syncwarp();
    }
    __syncthreads();

    // ---- block reduce np / ll / lcp ----
#pragma unroll
    for (int o = 16; o > 0; o >>= 1) {
        ll  += __shfl_down_sync(0xffffffffu, ll, o);
        lcp += __shfl_down_sync(0xffffffffu, lcp, o);
        np  += __shfl_down_sync(0xffffffffu, np, o);
    }
    if (lane == 0) { S->rf[wrp] = ll; S->rf2[wrp] = lcp; S->ri[wrp] = np; }
    __syncthreads();
    float ll_t = 0.0f, lcp_t = 0.0f;
    int   np_t = 0;
    if (tid < NWARPS) { ll_t = S->rf[tid]; lcp_t = S->rf2[tid]; np_t = S->ri[tid]; }
    if (tid < 32) {
#pragma unroll
        for (int o = 8; o > 0; o >>= 1) {
            ll_t  += __shfl_down_sync(0xffffffffu, ll_t, o);
            lcp_t += __shfl_down_sync(0xffffffffu, lcp_t, o);
            np_t  += __shfl_down_sync(0xffffffffu, np_t, o);
        }
    }
    if (tid == 0) S->bc[0] = np_t;
    __syncthreads();
    const int np_tot = S->bc[0];
    int k = 3 * np_tot;
    if (k > NP - 1) k = NP - 1;

    // ---- exact top-k sum via 3-round radix select ----
    float Ssum = 0.0f;
    if (k > 0) {
        unsigned prefix = 0u, pmask = 0u;
        const int shifts[3] = {21, 10, 0};
        const int rbits[3]  = {11, 11, 10};
        int kk = k;
        for (int r = 0; r < 3; r++) {
            for (int i = tid; i < 2048; i += NTHREADS) hist[i] = 0u;
            __syncthreads();
            const unsigned nb = 1u << rbits[r];
            for (int p = tid; p < ((NP + NTHREADS - 1) / NTHREADS) * NTHREADS; p += NTHREADS) {
                bool valid = p < NP;
                unsigned bb = valid ? __float_as_uint(S->lc[p]) : 0u;
                bool sel = valid && ((bb & pmask) == prefix);
                unsigned bin = sel ? ((bb >> shifts[r]) & (nb - 1u)) : 0xffffffffu;
                unsigned grp = __match_any_sync(0xffffffffu, bin);
                if (sel && lane == (__ffs(grp) - 1))
                    atomicAdd(&hist[bin], (unsigned)__popc(grp));
            }
            __syncthreads();
            // parallel suffix scan: thread t owns bins [4t, 4t+3]
            unsigned c0 = hist[tid * 4 + 0], c1 = hist[tid * 4 + 1];
            unsigned c2 = hist[tid * 4 + 2], c3 = hist[tid * 4 + 3];
            unsigned sloc = c0 + c1 + c2 + c3;
            unsigned suf = sloc;
#pragma unroll
            for (int o = 1; o < 32; o <<= 1) {
                unsigned v = __shfl_down_sync(0xffffffffu, suf, o);
                if (lane + o < 32) suf += v;
            }
            if (lane == 0) S->gsum[wrp] = suf;
            __syncthreads();
            unsigned above = 0;
            for (int w = wrp + 1; w < NWARPS; w++) above += S->gsum[w];
            unsigned excl3 = above + (suf - sloc);   // all bins above bin 4t+3
            unsigned excl2 = excl3 + c3;
            unsigned excl1 = excl2 + c2;
            unsigned excl0 = excl1 + c1;
            unsigned ukk = (unsigned)kk;
            if (excl3 < ukk && ukk <= excl3 + c3) { S->bc[1] = tid * 4 + 3; S->bc[2] = (int)(ukk - excl3); }
            if (excl2 < ukk && ukk <= excl2 + c2) { S->bc[1] = tid * 4 + 2; S->bc[2] = (int)(ukk - excl2); }
            if (excl1 < ukk && ukk <= excl1 + c1) { S->bc[1] = tid * 4 + 1; S->bc[2] = (int)(ukk - excl1); }
            if (excl0 < ukk && ukk <= excl0 + c0) { S->bc[1] = tid * 4 + 0; S->bc[2] = (int)(ukk - excl0); }
            __syncthreads();
            int chosen = S->bc[1];
            kk = S->bc[2];
            prefix |= ((unsigned)chosen) << shifts[r];
            pmask  |= ((1u << rbits[r]) - 1u) << shifts[r];
            __syncthreads();
        }
        const float tv = __uint_as_float(prefix);
        float sgt = 0.0f;
        int   cgt = 0;
        for (int p = tid; p < NP; p += NTHREADS) {
            float v = S->lc[p];
            if (__float_as_uint(v) > prefix) { sgt += v; cgt++; }
        }
#pragma unroll
        for (int o = 16; o > 0; o >>= 1) {
            sgt += __shfl_down_sync(0xffffffffu, sgt, o);
            cgt += __shfl_down_sync(0xffffffffu, cgt, o);
        }
        __syncthreads();
        if (lane == 0) { S->rf[wrp] = sgt; S->ri[wrp] = cgt; }
        __syncthreads();
        float sgt_t = 0.0f;
        int   cgt_t = 0;
        if (tid < NWARPS) { sgt_t = S->rf[tid]; cgt_t = S->ri[tid]; }
        if (tid < 32) {
#pragma unroll
            for (int o = 8; o > 0; o >>= 1) {
                sgt_t += __shfl_down_sync(0xffffffffu, sgt_t, o);
                cgt_t += __shfl_down_sync(0xffffffffu, cgt_t, o);
            }
        }
        if (tid == 0) Ssum = sgt_t + (float)(k - cgt_t) * tv;
    }

    // ---- publish per-batch partials; last CTA finalizes ----
    __shared__ bool slast;
    if (tid == 0) {
        g_bll[b] = ll_t;
        g_blc[b] = lcp_t + Ssum;
        g_bnp[b] = np_tot;
        __threadfence();
        unsigned t = atomicAdd(&g_arrive, 1u);
        slast = (t == gridDim.x - 1);
        if (slast) g_arrive = 0u;
    }
    __syncthreads();
    if (slast) {
        float fll = 0.0f, flc = 0.0f;
        int   fnp = 0;
        for (int i = tid; i < (int)gridDim.x; i += NTHREADS) {
            fll += g_bll[i]; flc += g_blc[i]; fnp += g_bnp[i];
        }
#pragma unroll
        for (int o = 16; o > 0; o >>= 1) {
            fll += __shfl_down_sync(0xffffffffu, fll, o);
            flc += __shfl_down_sync(0xffffffffu, flc, o);
            fnp += __shfl_down_sync(0xffffffffu, fnp, o);
        }
        if (lane == 0) { S->rf[wrp] = fll; S->rf2[wrp] = flc; S->ri[wrp] = fnp; }
        __syncthreads();
        if (tid == 0) {
            float tll = 0.0f, tlc = 0.0f;
            int tnp = 0;
            for (int w = 0; w < NWARPS; w++) { tll += S->rf[w]; tlc += S->rf2[w]; tnp += S->ri[w]; }
            float N = (float)tnp;
            out[0] = tll / N;
            out[1] = tlc / N;
        }
    }
}

extern "C" void kernel_launch(void* const* d_in, const int* in_sizes, int n_in,
                              void* d_out, int out_size) {
    const float* loc     = (const float*)d_in[0];
    const float* conf    = (const float*)d_in[1];
    const float* priors  = (const float*)d_in[2];
    const float* targets = (const float*)d_in[3];
    const int B = in_sizes[0] / (NP * 10);

    static int configured = 0;
    if (!configured) {
        cudaFuncSetAttribute(mb_main, cudaFuncAttributeMaxDynamicSharedMemorySize,
                             (int)sizeof(Smem));
        configured = 1;
    }
    mb_main<<<B, NTHREADS, sizeof(Smem)>>>(loc, conf, priors, targets, (float*)d_out);
}

// round 4
// speedup vs baseline: 1.8376x; 1.1236x over previous
#include <cuda_runtime.h>
#include <math.h>

#define NP 8732
#define NG 16
#define NC 21
#define NTHREADS 1024
#define NWARPS 32
#define NTILES 273

__device__ float g_bll[256];
__device__ float g_blc[256];
__device__ int   g_bnp[256];
__device__ unsigned g_arrive = 0;

struct __align__(16) Smem {
    float  stage[NWARPS * 672];    // conf staging; aliased as radix hist (8KB) later
    float  lc[NP];
    float  tg[NG * 11];
    float4 box[NG];
    float  taa[NG];
    unsigned char gp[NP + 4];      // gi | (pos<<4)
    float  rqv[NG * NWARPS];
    int    rqi[NG * NWARPS];
    int    bp[NG];
    float  rf[NWARPS];
    float  rf2[NWARPS];
    int    ri[NWARPS];
    unsigned gsum[NWARPS];
    int    bc[4];
};

__global__ void __launch_bounds__(NTHREADS, 1) mb_main(
    const float* __restrict__ loc_data,   // [B, NP, 10]
    const float* __restrict__ conf_data,  // [B, NP, 21]
    const float* __restrict__ priors,     // [NP, 4]
    const float* __restrict__ targets,    // [B, NG, 11]
    float* __restrict__ out)
{
    extern __shared__ char smem_raw[];
    Smem* S = (Smem*)smem_raw;
    unsigned* hist = (unsigned*)S->stage;

    const int b    = blockIdx.x;
    const int tid  = threadIdx.x;
    const int lane = tid & 31;
    const int wrp  = tid >> 5;

    for (int i = tid; i < NG * 11; i += NTHREADS)
        S->tg[i] = targets[b * NG * 11 + i];
    __syncthreads();
    if (tid < NG) {
        const float* t = S->tg + tid * 11;
        float4 bx = make_float4(t[0], t[1], t[2], t[3]);
        S->box[tid] = bx;
        S->taa[tid] = (bx.z - bx.x) * (bx.w - bx.y);
    }
    __syncthreads();

    // ---- pass 1: matching ----
    // per-GT best prior: (q, idx) with q = fast quotient; best-GT per prior + pos: exact rational
    float qv[NG];
    int   qi[NG];
#pragma unroll
    for (int g = 0; g < NG; g++) { qv[g] = -1.0f; qi[g] = 0x7fffffff; }

#pragma unroll 1
    for (int p = tid; p < NP; p += NTHREADS) {
        float4 pr = __ldg((const float4*)priors + p);
        float pax = pr.x - 0.5f * pr.z;
        float pay = pr.y - 0.5f * pr.w;
        float pbx = pr.x + 0.5f * pr.z;
        float pby = pr.y + 0.5f * pr.w;
        float pare = (pbx - pax) * (pby - pay);
        float bin_ = -1.0f, bdn_ = 1.0f;
        int bg = 0;
#pragma unroll
        for (int g = 0; g < NG; g++) {
            float4 t = S->box[g];
            float ix = fminf(t.z, pbx) - fmaxf(t.x, pax);
            float iy = fminf(t.w, pby) - fmaxf(t.y, pay);
            ix = fmaxf(ix, 0.0f);
            iy = fmaxf(iy, 0.0f);
            float inter = ix * iy;
            float den = (S->taa[g] + pare) - inter;   // > 0
            if (inter * bdn_ > bin_ * den) { bin_ = inter; bdn_ = den; bg = g; }
            float q = __fdividef(inter, den);
            if (q > qv[g]) { qv[g] = q; qi[g] = p; }
        }
        unsigned char posb = (bin_ >= 0.5f * bdn_) ? 0x10 : 0x00;
        S->gp[p] = (unsigned char)bg | posb;
    }

    // warp reduce per gt (q desc, idx asc)
#pragma unroll
    for (int g = 0; g < NG; g++) {
        float q = qv[g];
        int   i = qi[g];
#pragma unroll
        for (int o = 16; o > 0; o >>= 1) {
            float q2 = __shfl_down_sync(0xffffffffu, q, o);
            int   i2 = __shfl_down_sync(0xffffffffu, i, o);
            if (q2 > q || (q2 == q && i2 < i)) { q = q2; i = i2; }
        }
        if (lane == 0) { S->rqv[g * NWARPS + wrp] = q; S->rqi[g * NWARPS + wrp] = i; }
    }
    __syncthreads();
    if (tid < NG) {
        float q = S->rqv[tid * NWARPS];
        int   i = S->rqi[tid * NWARPS];
        for (int w = 1; w < NWARPS; w++) {
            float q2 = S->rqv[tid * NWARPS + w];
            int   i2 = S->rqi[tid * NWARPS + w];
            if (q2 > q || (q2 == q && i2 < i)) { q = q2; i = i2; }
        }
        S->bp[tid] = i;
    }
    __syncthreads();
    if (tid == 0) {
#pragma unroll
        for (int j = 0; j < NG; j++) S->gp[S->bp[j]] = (unsigned char)j | 0x10;
    }
    __syncthreads();

    // ---- pass 2: per-prior losses ----
    float ll = 0.0f, lcp = 0.0f;
    int   np = 0;
    float* stg = S->stage + wrp * 672;

#pragma unroll 1
    for (int tile = wrp; tile < NTILES; tile += NWARPS) {
        const int p0 = tile * 32;
        const int cnt = (NP - p0 < 32) ? (NP - p0) : 32;
        const int tcnt4 = (cnt * NC) >> 2;   // 21*cnt always divisible by 4 here
        const float4* cbase4 = (const float4*)(conf_data + ((size_t)b * NP + p0) * NC);
        float4* stg4 = (float4*)stg;
#pragma unroll
        for (int j = 0; j < 6; j++) {
            int idx2 = j * 32 + lane;
            if (idx2 < tcnt4) stg4[idx2] = __ldg(cbase4 + idx2);
        }
        __syncwarp();

        const int p = p0 + lane;
        if (p < NP) {
            unsigned gpv = S->gp[p];
            int gi = gpv & 15;
            int conf = (gpv & 0x10) ? ((int)S->tg[gi * 11 + 10] + 1) : 0;

            const float* row = stg + lane * NC;
            float cv[NC];
#pragma unroll
            for (int j = 0; j < NC; j++) cv[j] = row[j];
            float m = cv[0];
#pragma unroll
            for (int j = 1; j < NC; j++) m = fmaxf(m, cv[j]);
            float s = 0.0f;
#pragma unroll
            for (int j = 0; j < NC; j++) s += __expf(cv[j] - m);
            float lca = (m + __logf(s)) - row[conf];

            float lc = lca;
            if (conf > 0) {
                lc = 0.0f;
                np++;
                lcp += lca;
                const float* t = S->tg + gi * 11;
                float4 pr = __ldg((const float4*)priors + p);
                float vx = 0.1f * pr.z;
                float vy = 0.1f * pr.w;
                float lts[10];
                lts[0] = ((t[0] + t[2]) * 0.5f - pr.x) / vx;
                lts[1] = ((t[1] + t[3]) * 0.5f - pr.y) / vy;
                lts[2] = logf((t[2] - t[0]) / pr.z) / 0.2f;
                lts[3] = logf((t[3] - t[1]) / pr.w) / 0.2f;
                lts[4] = logf(t[4] / pr.z + 0.1f) / 0.2f;
                lts[5] = logf(t[5] / pr.w + 0.1f) / 0.2f;
                lts[6] = logf(t[6] / pr.z + 0.1f) / 0.2f;
                lts[7] = logf(t[7] / pr.w + 0.1f) / 0.2f;
                lts[8] = (t[8] - pr.x) / vx;
                lts[9] = (t[9] - pr.y) / vy;
                const float* ld = loc_data + ((size_t)b * NP + p) * 10;
#pragma unroll
                for (int j = 0; j < 10; j++) {
                    float d  = __ldg(ld + j) - lts[j];
                    float ad = fabsf(d);
                    ll += (ad < 1.0f) ? (0.5f * d) * d : (ad - 0.5f);
                }
            }
            S->lc[p] = lc;
        }
        __syncwarp();
    }
    __syncthreads();

    // ---- block reduce np / ll / lcp ----
#pragma unroll
    for (int o = 16; o > 0; o >>= 1) {
        ll  += __shfl_down_sync(0xffffffffu, ll, o);
        lcp += __shfl_down_sync(0xffffffffu, lcp, o);
        np  += __shfl_down_sync(0xffffffffu, np, o);
    }
    if (lane == 0) { S->rf[wrp] = ll; S->rf2[wrp] = lcp; S->ri[wrp] = np; }
    __syncthreads();
    if (tid < 32) {
        float ll_t = S->rf[tid], lcp_t = S->rf2[tid];
        int   np_t = S->ri[tid];
#pragma unroll
        for (int o = 16; o > 0; o >>= 1) {
            ll_t  += __shfl_down_sync(0xffffffffu, ll_t, o);
            lcp_t += __shfl_down_sync(0xffffffffu, lcp_t, o);
            np_t  += __shfl_down_sync(0xffffffffu, np_t, o);
        }
        if (tid == 0) {
            S->rf[0] = ll_t; S->rf2[0] = lcp_t; S->bc[0] = np_t;
        }
    }
    __syncthreads();
    const int np_tot = S->bc[0];
    const float ll_tot = S->rf[0];
    const float lcp_tot = S->rf2[0];
    int k = 3 * np_tot;
    if (k > NP - 1) k = NP - 1;

    // ---- exact top-k sum via 3-round radix select ----
    float Ssum = 0.0f;
    if (k > 0) {
        unsigned prefix = 0u, pmask = 0u;
        const int shifts[3] = {21, 10, 0};
        const int rbits[3]  = {11, 11, 10};
        int kk = k;
        for (int r = 0; r < 3; r++) {
            for (int i = tid; i < 2048; i += NTHREADS) hist[i] = 0u;
            __syncthreads();
            const unsigned nb = 1u << rbits[r];
#pragma unroll 1
            for (int p = tid; p < 9216; p += NTHREADS) {
                bool valid = p < NP;
                unsigned bb = valid ? __float_as_uint(S->lc[p]) : 0u;
                bool sel = valid && ((bb & pmask) == prefix);
                unsigned bin = sel ? ((bb >> shifts[r]) & (nb - 1u)) : 0xffffffffu;
                unsigned grp = __match_any_sync(0xffffffffu, bin);
                if (sel && lane == (__ffs(grp) - 1))
                    atomicAdd(&hist[bin], (unsigned)__popc(grp));
            }
            __syncthreads();
            // suffix scan: thread t owns bins [2t, 2t+1]
            unsigned c0 = hist[tid * 2 + 0], c1 = hist[tid * 2 + 1];
            unsigned sloc = c0 + c1;
            unsigned suf = sloc;
#pragma unroll
            for (int o = 1; o < 32; o <<= 1) {
                unsigned v = __shfl_down_sync(0xffffffffu, suf, o);
                if (lane + o < 32) suf += v;
            }
            if (lane == 0) S->gsum[wrp] = suf;
            __syncthreads();
            unsigned above = 0;
            for (int w = wrp + 1; w < NWARPS; w++) above += S->gsum[w];
            unsigned excl1 = above + (suf - sloc);
            unsigned excl0 = excl1 + c1;
            unsigned ukk = (unsigned)kk;
            if (excl1 < ukk && ukk <= excl1 + c1) { S->bc[1] = tid * 2 + 1; S->bc[2] = (int)(ukk - excl1); }
            if (excl0 < ukk && ukk <= excl0 + c0) { S->bc[1] = tid * 2 + 0; S->bc[2] = (int)(ukk - excl0); }
            __syncthreads();
            int chosen = S->bc[1];
            kk = S->bc[2];
            prefix |= ((unsigned)chosen) << shifts[r];
            pmask  |= ((1u << rbits[r]) - 1u) << shifts[r];
            __syncthreads();
        }
        const float tv = __uint_as_float(prefix);
        float sgt = 0.0f;
        int   cgt = 0;
#pragma unroll 1
        for (int p = tid; p < NP; p += NTHREADS) {
            float v = S->lc[p];
            if (__float_as_uint(v) > prefix) { sgt += v; cgt++; }
        }
#pragma unroll
        for (int o = 16; o > 0; o >>= 1) {
            sgt += __shfl_down_sync(0xffffffffu, sgt, o);
            cgt += __shfl_down_sync(0xffffffffu, cgt, o);
        }
        if (lane == 0) { S->rf[wrp] = sgt; S->ri[wrp] = cgt; }
        __syncthreads();
        if (tid == 0) {
            float sgt_t = 0.0f;
            int   cgt_t = 0;
            for (int w = 0; w < NWARPS; w++) { sgt_t += S->rf[w]; cgt_t += S->ri[w]; }
            Ssum = sgt_t + (float)(k - cgt_t) * tv;
        }
    }

    // ---- publish per-batch partials; last CTA finalizes ----
    __shared__ bool slast;
    if (tid == 0) {
        g_bll[b] = ll_tot;
        g_blc[b] = lcp_tot + Ssum;
        g_bnp[b] = np_tot;
        __threadfence();
        unsigned t = atomicAdd(&g_arrive, 1u);
        slast = (t == gridDim.x - 1);
        if (slast) g_arrive = 0u;
    }
    __syncthreads();
    if (slast) {
        float fll = 0.0f, flc = 0.0f;
        int   fnp = 0;
        for (int i = tid; i < (int)gridDim.x; i += NTHREADS) {
            fll += g_bll[i]; flc += g_blc[i]; fnp += g_bnp[i];
        }
#pragma unroll
        for (int o = 16; o > 0; o >>= 1) {
            fll += __shfl_down_sync(0xffffffffu, fll, o);
            flc += __shfl_down_sync(0xffffffffu, flc, o);
            fnp += __shfl_down_sync(0xffffffffu, fnp, o);
        }
        if (lane == 0) { S->rf[wrp] = fll; S->rf2[wrp] = flc; S->ri[wrp] = fnp; }
        __syncthreads();
        if (tid == 0) {
            float tll = 0.0f, tlc = 0.0f;
            int tnp = 0;
            for (int w = 0; w < NWARPS; w++) { tll += S->rf[w]; tlc += S->rf2[w]; tnp += S->ri[w]; }
            float N = (float)tnp;
            out[0] = tll / N;
            out[1] = tlc / N;
        }
    }
}

extern "C" void kernel_launch(void* const* d_in, const int* in_sizes, int n_in,
                              void* d_out, int out_size) {
    const float* loc     = (const float*)d_in[0];
    const float* conf    = (const float*)d_in[1];
    const float* priors  = (const float*)d_in[2];
    const float* targets = (const float*)d_in[3];
    const int B = in_sizes[0] / (NP * 10);

    cudaFuncSetAttribute(mb_main, cudaFuncAttributeMaxDynamicSharedMemorySize,
                         (int)sizeof(Smem));
    mb_main<<<B, NTHREADS, sizeof(Smem)>>>(loc, conf, priors, targets, (float*)d_out);
}